// round 2
// baseline (speedup 1.0000x reference)
#include <cuda_runtime.h>
#include <math.h>
#include <float.h>

#define S_LEN 2048
#define DIM_  4096
#define NH    32
#define NKV   8
#define HD    128

// Scratch (device globals: allocation-guard safe)
__device__ float g_q[(size_t)S_LEN * DIM_];
__device__ float g_k[(size_t)S_LEN * NKV * HD];
__device__ float g_v[(size_t)S_LEN * NKV * HD];
__device__ float g_attn[(size_t)S_LEN * DIM_];

// ---------------------------------------------------------------------------
// SGEMM: C[M,N] = A[M,K] @ B[K,N], row-major fp32.
// 128x128 tile, BK=8, 256 threads, 8x8 per-thread register tile.
// Requires M%128==0, N%128==0, K%8==0 (true for all shapes here).
// ---------------------------------------------------------------------------
__global__ __launch_bounds__(256, 2) void sgemm128(
    const float* __restrict__ A, const float* __restrict__ B,
    float* __restrict__ C, int M, int N, int K)
{
    __shared__ float As[8][129];   // transposed A tile, padded vs conflicts
    __shared__ float Bs[8][128];

    const int tid = threadIdx.x;
    const int bm = blockIdx.y, bn = blockIdx.x;
    const int ty = tid >> 4, tx = tid & 15;

    const float* Ab = A + (size_t)bm * 128 * K;
    const float* Bb = B + (size_t)bn * 128;

    const int rowA = tid >> 1, ksegA = (tid & 1) * 4;
    const int rowB = tid >> 5, colB = (tid & 31) * 4;

    float acc[8][8];
#pragma unroll
    for (int i = 0; i < 8; i++)
#pragma unroll
        for (int j = 0; j < 8; j++) acc[i][j] = 0.f;

    for (int k0 = 0; k0 < K; k0 += 8) {
        float4 va = *(const float4*)(Ab + (size_t)rowA * K + k0 + ksegA);
        float4 vb = *(const float4*)(Bb + (size_t)(k0 + rowB) * N + colB);
        __syncthreads();
        As[ksegA + 0][rowA] = va.x;
        As[ksegA + 1][rowA] = va.y;
        As[ksegA + 2][rowA] = va.z;
        As[ksegA + 3][rowA] = va.w;
        *(float4*)(&Bs[rowB][colB]) = vb;
        __syncthreads();
#pragma unroll
        for (int kk = 0; kk < 8; kk++) {
            float a[8], b[8];
#pragma unroll
            for (int i = 0; i < 8; i++) a[i] = As[kk][ty * 8 + i];
#pragma unroll
            for (int j = 0; j < 8; j++) b[j] = Bs[kk][tx * 8 + j];
#pragma unroll
            for (int i = 0; i < 8; i++)
#pragma unroll
                for (int j = 0; j < 8; j++)
                    acc[i][j] = fmaf(a[i], b[j], acc[i][j]);
        }
    }

    float* Cb = C + (size_t)(bm * 128 + ty * 8) * N + bn * 128 + tx * 8;
#pragma unroll
    for (int i = 0; i < 8; i++) {
        float4 v0 = make_float4(acc[i][0], acc[i][1], acc[i][2], acc[i][3]);
        float4 v1 = make_float4(acc[i][4], acc[i][5], acc[i][6], acc[i][7]);
        *(float4*)(Cb + (size_t)i * N)     = v0;
        *(float4*)(Cb + (size_t)i * N + 4) = v1;
    }
}

// ---------------------------------------------------------------------------
// RoPE: interleaved pairs (2i, 2i+1), cos/sin are [S, HD/2]
// ---------------------------------------------------------------------------
__global__ void rope_kernel(float* __restrict__ t, const float* __restrict__ cosv,
                            const float* __restrict__ sinv, int nheads, int total)
{
    int idx = blockIdx.x * blockDim.x + threadIdx.x;
    if (idx >= total) return;
    int pair = idx & 63;
    int h    = (idx >> 6) % nheads;
    int seq  = idx / (64 * nheads);
    float c = cosv[seq * 64 + pair];
    float s = sinv[seq * 64 + pair];
    float* p = t + (size_t)seq * nheads * HD + h * HD + pair * 2;
    float2 v = *(float2*)p;
    float re = v.x, im = v.y;
    v.x = re * c - im * s;
    v.y = re * s + im * c;
    *(float2*)p = v;
}

// ---------------------------------------------------------------------------
// Flash attention (fp32, causal, GQA kv = h/4).
// Block: 256 threads, one (head, 64-query tile). 64x64 score tiles.
// smem: Qs/Ks transposed [128][65], Vs [64][128], Ps [64][65].
// Per thread: 4 q-rows x 4 k-cols scores; 4 q-rows x 8 d-cols output.
// ---------------------------------------------------------------------------
__global__ __launch_bounds__(256, 1) void flash_attn(
    const float* __restrict__ Qg, const float* __restrict__ Kg,
    const float* __restrict__ Vg, float* __restrict__ Og)
{
    extern __shared__ float sm[];
    float* Qs = sm;                  // 128*65
    float* Ks = Qs + 128 * 65;       // 128*65
    float* Vs = Ks + 128 * 65;       // 64*128
    float* Ps = Vs + 64 * 128;       // 64*65

    const int qt = blockIdx.x, h = blockIdx.y;
    const int kvh = h >> 2;
    const int tid = threadIdx.x;
    const int ty = tid >> 4, tx = tid & 15;
    const float scale = 0.08838834764831845f;  // 1/sqrt(128)

    // Load Q tile transposed: Qs[d][q]
#pragma unroll
    for (int it = 0; it < 8; it++) {
        int idx = tid + it * 256;
        int q = idx >> 5, dg = (idx & 31) * 4;
        float4 v = *(const float4*)(Qg + (size_t)(qt * 64 + q) * DIM_ + h * HD + dg);
        Qs[(dg + 0) * 65 + q] = v.x;
        Qs[(dg + 1) * 65 + q] = v.y;
        Qs[(dg + 2) * 65 + q] = v.z;
        Qs[(dg + 3) * 65 + q] = v.w;
    }

    float o[4][8];
    float m[4], l[4];
#pragma unroll
    for (int i = 0; i < 4; i++) {
        m[i] = -INFINITY; l[i] = 0.f;
#pragma unroll
        for (int j = 0; j < 8; j++) o[i][j] = 0.f;
    }

    for (int kt = 0; kt <= qt; kt++) {
        __syncthreads();
        // Load K tile transposed Ks[d][k] and V tile direct Vs[k][d]
#pragma unroll
        for (int it = 0; it < 8; it++) {
            int idx = tid + it * 256;
            int k = idx >> 5, dg = (idx & 31) * 4;
            size_t off = (size_t)(kt * 64 + k) * (NKV * HD) + kvh * HD + dg;
            float4 kv = *(const float4*)(Kg + off);
            Ks[(dg + 0) * 65 + k] = kv.x;
            Ks[(dg + 1) * 65 + k] = kv.y;
            Ks[(dg + 2) * 65 + k] = kv.z;
            Ks[(dg + 3) * 65 + k] = kv.w;
            float4 vv = *(const float4*)(Vg + off);
            *(float4*)(Vs + k * 128 + dg) = vv;
        }
        __syncthreads();

        // S = Q K^T (64x64x128)
        float s4[4][4];
#pragma unroll
        for (int i = 0; i < 4; i++)
#pragma unroll
            for (int j = 0; j < 4; j++) s4[i][j] = 0.f;

        for (int d = 0; d < 128; d++) {
            float a[4], b[4];
#pragma unroll
            for (int i = 0; i < 4; i++) a[i] = Qs[d * 65 + ty * 4 + i];
#pragma unroll
            for (int j = 0; j < 4; j++) b[j] = Ks[d * 65 + tx * 4 + j];
#pragma unroll
            for (int i = 0; i < 4; i++)
#pragma unroll
                for (int j = 0; j < 4; j++)
                    s4[i][j] = fmaf(a[i], b[j], s4[i][j]);
        }

        const bool diag = (kt == qt);
#pragma unroll
        for (int i = 0; i < 4; i++)
#pragma unroll
            for (int j = 0; j < 4; j++) {
                float v = s4[i][j] * scale;
                if (diag && (tx * 4 + j > ty * 4 + i)) v = -INFINITY;
                s4[i][j] = v;
            }

        // Online softmax: per-row max / sum via 16-lane shfl reductions
        float mt[4], fac[4];
#pragma unroll
        for (int i = 0; i < 4; i++) {
            float v = fmaxf(fmaxf(s4[i][0], s4[i][1]), fmaxf(s4[i][2], s4[i][3]));
#pragma unroll
            for (int msk = 1; msk < 16; msk <<= 1)
                v = fmaxf(v, __shfl_xor_sync(0xffffffffu, v, msk));
            mt[i]  = fmaxf(m[i], v);
            fac[i] = expf(m[i] - mt[i]);
        }
#pragma unroll
        for (int i = 0; i < 4; i++) {
            float r = 0.f;
#pragma unroll
            for (int j = 0; j < 4; j++) {
                float p = expf(s4[i][j] - mt[i]);
                s4[i][j] = p; r += p;
            }
#pragma unroll
            for (int msk = 1; msk < 16; msk <<= 1)
                r += __shfl_xor_sync(0xffffffffu, r, msk);
            l[i] = l[i] * fac[i] + r;
            m[i] = mt[i];
#pragma unroll
            for (int j = 0; j < 8; j++) o[i][j] *= fac[i];
        }

        // Stage P to smem for the PV GEMM
#pragma unroll
        for (int i = 0; i < 4; i++)
#pragma unroll
            for (int j = 0; j < 4; j++)
                Ps[(ty * 4 + i) * 65 + tx * 4 + j] = s4[i][j];
        __syncthreads();

        // O += P @ V (64x128x64)
        for (int kk = 0; kk < 64; kk++) {
            float a[4];
#pragma unroll
            for (int i = 0; i < 4; i++) a[i] = Ps[(ty * 4 + i) * 65 + kk];
            float4 b0 = *(const float4*)(Vs + kk * 128 + tx * 8);
            float4 b1 = *(const float4*)(Vs + kk * 128 + tx * 8 + 4);
            float b[8] = {b0.x, b0.y, b0.z, b0.w, b1.x, b1.y, b1.z, b1.w};
#pragma unroll
            for (int i = 0; i < 4; i++)
#pragma unroll
                for (int j = 0; j < 8; j++)
                    o[i][j] = fmaf(a[i], b[j], o[i][j]);
        }
    }

    // Epilogue: normalize and store to [s, h*128+d] layout
#pragma unroll
    for (int i = 0; i < 4; i++) {
        float invl = 1.f / l[i];
        float4 v0 = make_float4(o[i][0] * invl, o[i][1] * invl,
                                o[i][2] * invl, o[i][3] * invl);
        float4 v1 = make_float4(o[i][4] * invl, o[i][5] * invl,
                                o[i][6] * invl, o[i][7] * invl);
        float* dst = Og + (size_t)(qt * 64 + ty * 4 + i) * DIM_ + h * HD + tx * 8;
        *(float4*)dst       = v0;
        *(float4*)(dst + 4) = v1;
    }
}

// ---------------------------------------------------------------------------
// Launcher
// ---------------------------------------------------------------------------
static const int FLASH_SMEM = (128 * 65 + 128 * 65 + 64 * 128 + 64 * 65) * 4; // 115968 B

extern "C" void kernel_launch(void* const* d_in, const int* in_sizes, int n_in,
                              void* d_out, int out_size)
{
    const float* x  = (const float*)d_in[0];
    const float* wq = (const float*)d_in[1];
    const float* wk = (const float*)d_in[2];
    const float* wv = (const float*)d_in[3];
    const float* wo = (const float*)d_in[4];
    const float* fc = (const float*)d_in[5];
    const float* fs = (const float*)d_in[6];
    // d_in[7] = mask: causal, handled analytically in flash_attn
    float* out = (float*)d_out;

    float *q, *k, *v, *attn;
    cudaGetSymbolAddress((void**)&q,    g_q);
    cudaGetSymbolAddress((void**)&k,    g_k);
    cudaGetSymbolAddress((void**)&v,    g_v);
    cudaGetSymbolAddress((void**)&attn, g_attn);

    cudaFuncSetAttribute(flash_attn,
                         cudaFuncAttributeMaxDynamicSharedMemorySize, FLASH_SMEM);

    dim3 blk(256);
    // Projections
    sgemm128<<<dim3(DIM_ / 128,       S_LEN / 128), blk>>>(x, wq, q, S_LEN, DIM_,     DIM_);
    sgemm128<<<dim3((NKV * HD) / 128, S_LEN / 128), blk>>>(x, wk, k, S_LEN, NKV * HD, DIM_);
    sgemm128<<<dim3((NKV * HD) / 128, S_LEN / 128), blk>>>(x, wv, v, S_LEN, NKV * HD, DIM_);
    // RoPE
    int totq = S_LEN * NH * 64;
    rope_kernel<<<(totq + 255) / 256, 256>>>(q, fc, fs, NH, totq);
    int totk = S_LEN * NKV * 64;
    rope_kernel<<<(totk + 255) / 256, 256>>>(k, fc, fs, NKV, totk);
    // Attention
    flash_attn<<<dim3(S_LEN / 64, NH), blk, FLASH_SMEM>>>(q, k, v, attn);
    // Output projection
    sgemm128<<<dim3(DIM_ / 128, S_LEN / 128), blk>>>(attn, wo, out, S_LEN, DIM_, DIM_);
}

// round 4
// speedup vs baseline: 1.9618x; 1.9618x over previous
#include <cuda_runtime.h>
#include <math.h>
#include <float.h>

#define S_LEN 2048
#define DIM_  4096
#define NH    32
#define NKV   8
#define HD    128

// Scratch (device globals: allocation-guard safe)
__device__ float g_q[(size_t)S_LEN * DIM_];
__device__ float g_k[(size_t)S_LEN * NKV * HD];
__device__ float g_v[(size_t)S_LEN * NKV * HD];
__device__ float g_attn[(size_t)S_LEN * DIM_];

__device__ __forceinline__ float to_tf32(float x) {
    float r;
    asm("cvt.rna.tf32.f32 %0, %1;" : "=f"(r) : "f"(x));
    return r;
}

__device__ __forceinline__ void mma_tf32(float* c, const float* a, const float* b) {
    asm volatile(
        "mma.sync.aligned.m16n8k8.row.col.f32.tf32.tf32.f32 "
        "{%0,%1,%2,%3}, {%4,%5,%6,%7}, {%8,%9}, {%0,%1,%2,%3};"
        : "+f"(c[0]), "+f"(c[1]), "+f"(c[2]), "+f"(c[3])
        : "r"(__float_as_uint(a[0])), "r"(__float_as_uint(a[1])),
          "r"(__float_as_uint(a[2])), "r"(__float_as_uint(a[3])),
          "r"(__float_as_uint(b[0])), "r"(__float_as_uint(b[1])));
}

// ---------------------------------------------------------------------------
// TF32 tensor-core GEMM: C[M,N] = A[M,K] @ B[K,N], fp32 storage.
// 128x128 tile, BK=16, 256 threads (8 warps, 4x2), warp tile 32x64.
// Requires M%128==0, N%128==0, K%16==0.
// ---------------------------------------------------------------------------
__global__ __launch_bounds__(256, 2) void mma_gemm(
    const float* __restrict__ A, const float* __restrict__ B,
    float* __restrict__ C, int M, int N, int K)
{
    __shared__ float As[16][136];   // [k][m], stride 136 -> conflict-free frags
    __shared__ float Bs[16][136];   // [k][n]

    const int tid  = threadIdx.x;
    const int warp = tid >> 5, lane = tid & 31;
    const int wm = warp >> 1, wn = warp & 1;
    const int m0w = wm * 32, n0w = wn * 64;
    const int bm = blockIdx.y * 128, bn = blockIdx.x * 128;
    const int lr = lane >> 2, lc = lane & 3;   // frag row-group / k-col

    // gmem load mapping
    const int arow = tid >> 1, acol = (tid & 1) * 8;
    const int bkrow = tid >> 5;            // 0..7
    const int bcol = lane * 4;

    float acc[2][8][4];
#pragma unroll
    for (int i = 0; i < 2; i++)
#pragma unroll
        for (int j = 0; j < 8; j++)
#pragma unroll
            for (int r = 0; r < 4; r++) acc[i][j][r] = 0.f;

    const float* Arow = A + (size_t)(bm + arow) * K;
    const float* Bb   = B + bn;

    for (int k0 = 0; k0 < K; k0 += 16) {
        float4 va0 = *(const float4*)(Arow + k0 + acol);
        float4 va1 = *(const float4*)(Arow + k0 + acol + 4);
        float4 vb0 = *(const float4*)(Bb + (size_t)(k0 + bkrow) * N + bcol);
        float4 vb1 = *(const float4*)(Bb + (size_t)(k0 + bkrow + 8) * N + bcol);
        __syncthreads();
        As[acol + 0][arow] = to_tf32(va0.x);
        As[acol + 1][arow] = to_tf32(va0.y);
        As[acol + 2][arow] = to_tf32(va0.z);
        As[acol + 3][arow] = to_tf32(va0.w);
        As[acol + 4][arow] = to_tf32(va1.x);
        As[acol + 5][arow] = to_tf32(va1.y);
        As[acol + 6][arow] = to_tf32(va1.z);
        As[acol + 7][arow] = to_tf32(va1.w);
        Bs[bkrow][bcol + 0] = to_tf32(vb0.x);
        Bs[bkrow][bcol + 1] = to_tf32(vb0.y);
        Bs[bkrow][bcol + 2] = to_tf32(vb0.z);
        Bs[bkrow][bcol + 3] = to_tf32(vb0.w);
        Bs[bkrow + 8][bcol + 0] = to_tf32(vb1.x);
        Bs[bkrow + 8][bcol + 1] = to_tf32(vb1.y);
        Bs[bkrow + 8][bcol + 2] = to_tf32(vb1.z);
        Bs[bkrow + 8][bcol + 3] = to_tf32(vb1.w);
        __syncthreads();

#pragma unroll
        for (int ks = 0; ks < 2; ks++) {
            const int kb = ks * 8;
            float af[2][4], bf[8][2];
#pragma unroll
            for (int im = 0; im < 2; im++) {
                const int m0 = m0w + im * 16 + lr;
                af[im][0] = As[kb + lc][m0];
                af[im][1] = As[kb + lc][m0 + 8];
                af[im][2] = As[kb + 4 + lc][m0];
                af[im][3] = As[kb + 4 + lc][m0 + 8];
            }
#pragma unroll
            for (int in_ = 0; in_ < 8; in_++) {
                const int n0 = n0w + in_ * 8 + lr;
                bf[in_][0] = Bs[kb + lc][n0];
                bf[in_][1] = Bs[kb + 4 + lc][n0];
            }
#pragma unroll
            for (int im = 0; im < 2; im++)
#pragma unroll
                for (int in_ = 0; in_ < 8; in_++)
                    mma_tf32(acc[im][in_], af[im], bf[in_]);
        }
    }

    // Epilogue: c0,c1 at (r, 2c),(r,2c+1); c2,c3 at (r+8, ...)
    float* Cb = C + (size_t)(bm + m0w + lr) * N + bn + n0w + lc * 2;
#pragma unroll
    for (int im = 0; im < 2; im++)
#pragma unroll
        for (int in_ = 0; in_ < 8; in_++) {
            float* p = Cb + (size_t)(im * 16) * N + in_ * 8;
            *(float2*)p = make_float2(acc[im][in_][0], acc[im][in_][1]);
            *(float2*)(p + (size_t)8 * N) = make_float2(acc[im][in_][2], acc[im][in_][3]);
        }
}

// ---------------------------------------------------------------------------
// RoPE: interleaved pairs (2i, 2i+1), cos/sin are [S, HD/2]
// ---------------------------------------------------------------------------
__global__ void rope_kernel(float* __restrict__ t, const float* __restrict__ cosv,
                            const float* __restrict__ sinv, int nheads, int total)
{
    int idx = blockIdx.x * blockDim.x + threadIdx.x;
    if (idx >= total) return;
    int pair = idx & 63;
    int h    = (idx >> 6) % nheads;
    int seq  = idx / (64 * nheads);
    float c = cosv[seq * 64 + pair];
    float s = sinv[seq * 64 + pair];
    float* p = t + (size_t)seq * nheads * HD + h * HD + pair * 2;
    float2 v = *(float2*)p;
    float re = v.x, im = v.y;
    v.x = re * c - im * s;
    v.y = re * s + im * c;
    *(float2*)p = v;
}

// ---------------------------------------------------------------------------
// Flash attention (fp32 SIMT, causal, GQA kv = h/4). Unchanged from R1.
// ---------------------------------------------------------------------------
__global__ __launch_bounds__(256, 1) void flash_attn(
    const float* __restrict__ Qg, const float* __restrict__ Kg,
    const float* __restrict__ Vg, float* __restrict__ Og)
{
    extern __shared__ float sm[];
    float* Qs = sm;                  // 128*65
    float* Ks = Qs + 128 * 65;       // 128*65
    float* Vs = Ks + 128 * 65;       // 64*128
    float* Ps = Vs + 64 * 128;       // 64*65

    const int qt = blockIdx.x, h = blockIdx.y;
    const int kvh = h >> 2;
    const int tid = threadIdx.x;
    const int ty = tid >> 4, tx = tid & 15;
    const float scale = 0.08838834764831845f;  // 1/sqrt(128)

#pragma unroll
    for (int it = 0; it < 8; it++) {
        int idx = tid + it * 256;
        int q = idx >> 5, dg = (idx & 31) * 4;
        float4 v = *(const float4*)(Qg + (size_t)(qt * 64 + q) * DIM_ + h * HD + dg);
        Qs[(dg + 0) * 65 + q] = v.x;
        Qs[(dg + 1) * 65 + q] = v.y;
        Qs[(dg + 2) * 65 + q] = v.z;
        Qs[(dg + 3) * 65 + q] = v.w;
    }

    float o[4][8];
    float m[4], l[4];
#pragma unroll
    for (int i = 0; i < 4; i++) {
        m[i] = -INFINITY; l[i] = 0.f;
#pragma unroll
        for (int j = 0; j < 8; j++) o[i][j] = 0.f;
    }

    for (int kt = 0; kt <= qt; kt++) {
        __syncthreads();
#pragma unroll
        for (int it = 0; it < 8; it++) {
            int idx = tid + it * 256;
            int k = idx >> 5, dg = (idx & 31) * 4;
            size_t off = (size_t)(kt * 64 + k) * (NKV * HD) + kvh * HD + dg;
            float4 kv = *(const float4*)(Kg + off);
            Ks[(dg + 0) * 65 + k] = kv.x;
            Ks[(dg + 1) * 65 + k] = kv.y;
            Ks[(dg + 2) * 65 + k] = kv.z;
            Ks[(dg + 3) * 65 + k] = kv.w;
            float4 vv = *(const float4*)(Vg + off);
            *(float4*)(Vs + k * 128 + dg) = vv;
        }
        __syncthreads();

        float s4[4][4];
#pragma unroll
        for (int i = 0; i < 4; i++)
#pragma unroll
            for (int j = 0; j < 4; j++) s4[i][j] = 0.f;

        for (int d = 0; d < 128; d++) {
            float a[4], b[4];
#pragma unroll
            for (int i = 0; i < 4; i++) a[i] = Qs[d * 65 + ty * 4 + i];
#pragma unroll
            for (int j = 0; j < 4; j++) b[j] = Ks[d * 65 + tx * 4 + j];
#pragma unroll
            for (int i = 0; i < 4; i++)
#pragma unroll
                for (int j = 0; j < 4; j++)
                    s4[i][j] = fmaf(a[i], b[j], s4[i][j]);
        }

        const bool diag = (kt == qt);
#pragma unroll
        for (int i = 0; i < 4; i++)
#pragma unroll
            for (int j = 0; j < 4; j++) {
                float v = s4[i][j] * scale;
                if (diag && (tx * 4 + j > ty * 4 + i)) v = -INFINITY;
                s4[i][j] = v;
            }

        float mt[4], fac[4];
#pragma unroll
        for (int i = 0; i < 4; i++) {
            float v = fmaxf(fmaxf(s4[i][0], s4[i][1]), fmaxf(s4[i][2], s4[i][3]));
#pragma unroll
            for (int msk = 1; msk < 16; msk <<= 1)
                v = fmaxf(v, __shfl_xor_sync(0xffffffffu, v, msk));
            mt[i]  = fmaxf(m[i], v);
            fac[i] = expf(m[i] - mt[i]);
        }
#pragma unroll
        for (int i = 0; i < 4; i++) {
            float r = 0.f;
#pragma unroll
            for (int j = 0; j < 4; j++) {
                float p = expf(s4[i][j] - mt[i]);
                s4[i][j] = p; r += p;
            }
#pragma unroll
            for (int msk = 1; msk < 16; msk <<= 1)
                r += __shfl_xor_sync(0xffffffffu, r, msk);
            l[i] = l[i] * fac[i] + r;
            m[i] = mt[i];
#pragma unroll
            for (int j = 0; j < 8; j++) o[i][j] *= fac[i];
        }

#pragma unroll
        for (int i = 0; i < 4; i++)
#pragma unroll
            for (int j = 0; j < 4; j++)
                Ps[(ty * 4 + i) * 65 + tx * 4 + j] = s4[i][j];
        __syncthreads();

        for (int kk = 0; kk < 64; kk++) {
            float a[4];
#pragma unroll
            for (int i = 0; i < 4; i++) a[i] = Ps[(ty * 4 + i) * 65 + kk];
            float4 b0 = *(const float4*)(Vs + kk * 128 + tx * 8);
            float4 b1 = *(const float4*)(Vs + kk * 128 + tx * 8 + 4);
            float b[8] = {b0.x, b0.y, b0.z, b0.w, b1.x, b1.y, b1.z, b1.w};
#pragma unroll
            for (int i = 0; i < 4; i++)
#pragma unroll
                for (int j = 0; j < 8; j++)
                    o[i][j] = fmaf(a[i], b[j], o[i][j]);
        }
    }

#pragma unroll
    for (int i = 0; i < 4; i++) {
        float invl = 1.f / l[i];
        float4 v0 = make_float4(o[i][0] * invl, o[i][1] * invl,
                                o[i][2] * invl, o[i][3] * invl);
        float4 v1 = make_float4(o[i][4] * invl, o[i][5] * invl,
                                o[i][6] * invl, o[i][7] * invl);
        float* dst = Og + (size_t)(qt * 64 + ty * 4 + i) * DIM_ + h * HD + tx * 8;
        *(float4*)dst       = v0;
        *(float4*)(dst + 4) = v1;
    }
}

// ---------------------------------------------------------------------------
// Launcher
// ---------------------------------------------------------------------------
static const int FLASH_SMEM = (128 * 65 + 128 * 65 + 64 * 128 + 64 * 65) * 4; // 115968 B

extern "C" void kernel_launch(void* const* d_in, const int* in_sizes, int n_in,
                              void* d_out, int out_size)
{
    const float* x  = (const float*)d_in[0];
    const float* wq = (const float*)d_in[1];
    const float* wk = (const float*)d_in[2];
    const float* wv = (const float*)d_in[3];
    const float* wo = (const float*)d_in[4];
    const float* fc = (const float*)d_in[5];
    const float* fs = (const float*)d_in[6];
    float* out = (float*)d_out;

    float *q, *k, *v, *attn;
    cudaGetSymbolAddress((void**)&q,    g_q);
    cudaGetSymbolAddress((void**)&k,    g_k);
    cudaGetSymbolAddress((void**)&v,    g_v);
    cudaGetSymbolAddress((void**)&attn, g_attn);

    cudaFuncSetAttribute(flash_attn,
                         cudaFuncAttributeMaxDynamicSharedMemorySize, FLASH_SMEM);

    dim3 blk(256);
    // Projections (TF32 tensor cores)
    mma_gemm<<<dim3(DIM_ / 128,       S_LEN / 128), blk>>>(x, wq, q, S_LEN, DIM_,     DIM_);
    mma_gemm<<<dim3((NKV * HD) / 128, S_LEN / 128), blk>>>(x, wk, k, S_LEN, NKV * HD, DIM_);
    mma_gemm<<<dim3((NKV * HD) / 128, S_LEN / 128), blk>>>(x, wv, v, S_LEN, NKV * HD, DIM_);
    // RoPE
    int totq = S_LEN * NH * 64;
    rope_kernel<<<(totq + 255) / 256, 256>>>(q, fc, fs, NH, totq);
    int totk = S_LEN * NKV * 64;
    rope_kernel<<<(totk + 255) / 256, 256>>>(k, fc, fs, NKV, totk);
    // Attention
    flash_attn<<<dim3(S_LEN / 64, NH), blk, FLASH_SMEM>>>(q, k, v, attn);
    // Output projection (TF32 tensor cores)
    mma_gemm<<<dim3(DIM_ / 128, S_LEN / 128), blk>>>(attn, wo, out, S_LEN, DIM_, DIM_);
}